// round 2
// baseline (speedup 1.0000x reference)
#include <cuda_runtime.h>
#include <math.h>
#include <stdint.h>

// ---------------------------------------------------------------------------
// HierarchicalClassifier: fused skinny-GEMM + sigmoid/softmax epilogue.
//   features : (16384, 2048) f32
//   top_W    : (8, 2048)     f32
//   top_b    : (8,)          f32
//   bottom_W : (8, 2048, 16) f32
//   bottom_b : (8, 16)       f32
//   out      : (16384, 128)  f32
//
// logits[b, n] for n in [0,136): n<8 -> top gate, n>=8 -> bottom expert t=(n-8)/16,
// class c=(n-8)%16. out[b, t*16+c] = sigmoid(logit_top[t]) * softmax_c(logit_bot[t,:])
// ---------------------------------------------------------------------------

#define B_ROWS  16384
#define D_K     2048
#define N_TOPL  8
#define N_CLASS 16
#define N_REAL  136
#define N_PAD   160   // pad to 160 so 32 threads x TN=5 tiles cleanly; pad cols zeroed

// Scratch (allocation-free rule: __device__ globals)
__device__ float g_W[D_K * N_PAD];     // packed weights, [k][n] row-major, 1.31 MB
__device__ float g_bias[N_PAD];

// ---------------------------------------------------------------------------
// Kernel 0: gather top_W / bottom_W into one (K, N_PAD) matrix + packed bias.
// ---------------------------------------------------------------------------
__global__ void pack_kernel(const float* __restrict__ topW,
                            const float* __restrict__ topb,
                            const float* __restrict__ botW,
                            const float* __restrict__ botb) {
    int idx = blockIdx.x * blockDim.x + threadIdx.x;
    if (idx < D_K * N_PAD) {
        int k = idx / N_PAD;
        int n = idx - k * N_PAD;
        float v = 0.0f;
        if (n < N_TOPL) {
            v = topW[n * D_K + k];                       // top_W is (8, 2048)
        } else if (n < N_REAL) {
            int t = (n - N_TOPL) >> 4;
            int c = (n - N_TOPL) & 15;
            v = botW[((size_t)t * D_K + k) * N_CLASS + c];  // bottom_W is (8, 2048, 16)
        }
        g_W[idx] = v;
    }
    if (idx < N_PAD) {
        float b = 0.0f;
        if (idx < N_TOPL) b = topb[idx];
        else if (idx < N_REAL) {
            int t = (idx - N_TOPL) >> 4;
            int c = (idx - N_TOPL) & 15;
            b = botb[t * N_CLASS + c];
        }
        g_bias[idx] = b;
    }
}

// ---------------------------------------------------------------------------
// Kernel 1: tiled fp32 GEMM (M=16384, N=160, K=2048) + fused epilogue.
//   BM=64, BN=160 (all columns -> epilogue stays in-block), BK=32.
//   256 threads; per-thread tile TM=8 x TN=5.
// ---------------------------------------------------------------------------
constexpr int BM = 64;
constexpr int BN = 160;
constexpr int BK = 32;
constexpr int TM = 8;
constexpr int TN = 5;
constexpr int APAD = 1;                 // As row padding: +1 float, conflict-free
constexpr int SMEM_FLOATS = BM * BN;    // 10240 floats (40 KB): reused as logits

__global__ __launch_bounds__(256, 4)
void hc_kernel(const float* __restrict__ A, float* __restrict__ out) {
    __shared__ float sm[SMEM_FLOATS];
    float* As = sm;                        // [BK][BM+APAD] = 32*65 = 2080 floats
    float* Bs = sm + BK * (BM + APAD);     // [BK][BN]      = 5120 floats

    const int tid = threadIdx.x;
    const int tx  = tid & 31;   // N dir: 32 threads * TN=5 -> 160
    const int ty  = tid >> 5;   // M dir:  8 threads * TM=8 -> 64
    const int row0 = blockIdx.x * BM;

    float acc[TM][TN];
    #pragma unroll
    for (int i = 0; i < TM; i++)
        #pragma unroll
        for (int j = 0; j < TN; j++)
            acc[i][j] = 0.0f;

    for (int kt = 0; kt < D_K; kt += BK) {
        // ---- load A tile (64 x 32), transposed into As[k][m] ----
        // 512 float4 / 256 threads = 2 each
        #pragma unroll
        for (int p = 0; p < 2; p++) {
            int idx = tid + p * 256;
            int ar  = idx >> 3;          // 0..63
            int ac  = (idx & 7) << 2;    // 0,4,...,28
            float4 v = *(const float4*)&A[(size_t)(row0 + ar) * D_K + kt + ac];
            As[(ac + 0) * (BM + APAD) + ar] = v.x;
            As[(ac + 1) * (BM + APAD) + ar] = v.y;
            As[(ac + 2) * (BM + APAD) + ar] = v.z;
            As[(ac + 3) * (BM + APAD) + ar] = v.w;
        }
        // ---- load B tile (32 x 160) ----
        // 1280 float4 / 256 threads = 5 each
        #pragma unroll
        for (int p = 0; p < 5; p++) {
            int idx = tid + p * 256;
            int br  = idx / 40;          // 0..31
            int bc  = (idx - br * 40) << 2;
            *(float4*)&Bs[br * BN + bc] =
                *(const float4*)&g_W[(size_t)(kt + br) * N_PAD + bc];
        }
        __syncthreads();

        #pragma unroll
        for (int k = 0; k < BK; k++) {
            float a[TM], b[TN];
            #pragma unroll
            for (int i = 0; i < TM; i++) a[i] = As[k * (BM + APAD) + ty * TM + i];
            #pragma unroll
            for (int j = 0; j < TN; j++) b[j] = Bs[k * BN + tx * TN + j];
            #pragma unroll
            for (int i = 0; i < TM; i++)
                #pragma unroll
                for (int j = 0; j < TN; j++)
                    acc[i][j] = fmaf(a[i], b[j], acc[i][j]);
        }
        __syncthreads();
    }

    // ---- stage logits (+bias) into SMEM, full [64][160] tile ----
    float bias[TN];
    #pragma unroll
    for (int j = 0; j < TN; j++) bias[j] = g_bias[tx * TN + j];
    #pragma unroll
    for (int i = 0; i < TM; i++)
        #pragma unroll
        for (int j = 0; j < TN; j++)
            sm[(ty * TM + i) * BN + tx * TN + j] = acc[i][j] + bias[j];
    __syncthreads();

    // ---- epilogue: 64 rows x 8 top-labels = 512 tasks, 2 per thread ----
    #pragma unroll
    for (int p = 0; p < 2; p++) {
        int task = tid + p * 256;
        int r = task >> 3;       // 0..63
        int t = task & 7;        // 0..7
        const float* Lr = &sm[r * BN];

        float gate = 1.0f / (1.0f + expf(-Lr[t]));

        float l[N_CLASS];
        float mx = -1e30f;
        #pragma unroll
        for (int c = 0; c < N_CLASS; c++) {
            l[c] = Lr[N_TOPL + t * N_CLASS + c];
            mx = fmaxf(mx, l[c]);
        }
        float s = 0.0f;
        #pragma unroll
        for (int c = 0; c < N_CLASS; c++) {
            l[c] = expf(l[c] - mx);
            s += l[c];
        }
        float scale = gate / s;

        float* op = &out[(size_t)(row0 + r) * (N_TOPL * N_CLASS) + t * N_CLASS];
        #pragma unroll
        for (int q = 0; q < 4; q++) {
            float4 v;
            v.x = l[q * 4 + 0] * scale;
            v.y = l[q * 4 + 1] * scale;
            v.z = l[q * 4 + 2] * scale;
            v.w = l[q * 4 + 3] * scale;
            ((float4*)op)[q] = v;
        }
    }
}

// ---------------------------------------------------------------------------
// Launch
// ---------------------------------------------------------------------------
extern "C" void kernel_launch(void* const* d_in, const int* in_sizes, int n_in,
                              void* d_out, int out_size) {
    const float* features = (const float*)d_in[0];
    const float* topW     = (const float*)d_in[1];
    const float* topb     = (const float*)d_in[2];
    const float* botW     = (const float*)d_in[3];
    const float* botb     = (const float*)d_in[4];
    float* out = (float*)d_out;

    pack_kernel<<<(D_K * N_PAD + 255) / 256, 256>>>(topW, topb, botW, botb);
    hc_kernel<<<B_ROWS / BM, 256>>>(features, out);
}

// round 4
// speedup vs baseline: 2.6212x; 2.6212x over previous
#include <cuda_runtime.h>
#include <cuda_bf16.h>
#include <stdint.h>
#include <math.h>

// ---------------------------------------------------------------------------
// HierarchicalClassifier via warp-level bf16 mma.sync (HMMA) on sm_103a.
//   logits[16384,136] = features[16384,2048] @ Wpacked[2048,136] + bias
//   fp32 emulated: Ah*Bh + Ah*Bl + Al*Bh (bf16 hi/lo split, 3 MMAs).
//   Packed cols: [0,128) bottom (t=n>>4, c=n&15), [128,136) top gate, pad->160.
// ---------------------------------------------------------------------------

#define D_K   2048
#define N_PAD 160
#define N_REAL 136

__device__ __nv_bfloat16 g_Bh[N_PAD * D_K];   // [n][k] K-major
__device__ __nv_bfloat16 g_Bl[N_PAD * D_K];
__device__ float         g_bias[N_PAD];

// ---------------------------------------------------------------------------
__global__ void pack_kernel(const float* __restrict__ topW,
                            const float* __restrict__ topb,
                            const float* __restrict__ botW,
                            const float* __restrict__ botb) {
    int idx = blockIdx.x * blockDim.x + threadIdx.x;
    if (idx < N_PAD * D_K) {
        int n = idx / D_K, k = idx - n * D_K;
        float v = 0.0f;
        if (n < 128) {
            int t = n >> 4, c = n & 15;
            v = botW[((size_t)t * D_K + k) * 16 + c];
        } else if (n < N_REAL) {
            v = topW[(n - 128) * D_K + k];
        }
        __nv_bfloat16 hi = __float2bfloat16(v);
        g_Bh[idx] = hi;
        g_Bl[idx] = __float2bfloat16(v - __bfloat162float(hi));
    }
    if (idx < N_PAD) {
        float b = 0.0f;
        if (idx < 128)         b = botb[idx];
        else if (idx < N_REAL) b = topb[idx - 128];
        g_bias[idx] = b;
    }
}

// ---------------------------------------------------------------------------
__device__ __forceinline__ uint32_t smem_u32(const void* p) {
    uint32_t a;
    asm("{ .reg .u64 t; cvta.to.shared.u64 t, %1; cvt.u32.u64 %0, t; }"
        : "=r"(a) : "l"(p));
    return a;
}

#define LDSM_X4(r0, r1, r2, r3, addr) \
    asm volatile("ldmatrix.sync.aligned.m8n8.x4.shared.b16 {%0,%1,%2,%3}, [%4];" \
        : "=r"(r0), "=r"(r1), "=r"(r2), "=r"(r3) : "r"(addr))

#define MMA_BF16(d, a, b) \
    asm volatile("mma.sync.aligned.m16n8k16.row.col.f32.bf16.bf16.f32 " \
        "{%0,%1,%2,%3}, {%4,%5,%6,%7}, {%8,%9}, {%0,%1,%2,%3};" \
        : "+f"((d)[0]), "+f"((d)[1]), "+f"((d)[2]), "+f"((d)[3]) \
        : "r"((a)[0]), "r"((a)[1]), "r"((a)[2]), "r"((a)[3]), \
          "r"((b)[0]), "r"((b)[1]))

#define CP16(dst, src) \
    asm volatile("cp.async.cg.shared.global [%0], [%1], 16;" \
        :: "r"(dst), "l"(src) : "memory")
#define CP_COMMIT() asm volatile("cp.async.commit_group;" ::: "memory")
#define CP_WAIT0()  asm volatile("cp.async.wait_group 0;" ::: "memory")

// split 2 fp32 -> packed bf16 hi pair + lo pair
__device__ __forceinline__ void split2(float v0, float v1, uint32_t& h, uint32_t& l) {
    uint32_t hp;
    asm("cvt.rn.bf16x2.f32 %0, %1, %2;" : "=r"(hp) : "f"(v1), "f"(v0));
    float h0 = __uint_as_float(hp << 16);
    float h1 = __uint_as_float(hp & 0xffff0000u);
    uint32_t lp;
    asm("cvt.rn.bf16x2.f32 %0, %1, %2;" : "=r"(lp) : "f"(v1 - h1), "f"(v0 - h0));
    h = hp; l = lp;
}

// ---------------------------------------------------------------------------
// SMEM stage layout (rows padded to 80B for conflict-free LDSM/STS):
//   Ahi @0 (128*80), Alo @10240, Bhi @20480 (160*80), Blo @33280. STAGE=46080.
// ---------------------------------------------------------------------------
constexpr int STAGE    = 46080;
constexpr int SMEM_DYN = 2 * STAGE;   // 92160; logits (80KB) reuses this

__global__ __launch_bounds__(256, 1)
void hc_mma_kernel(const float* __restrict__ A, float* __restrict__ out) {
    extern __shared__ char sm[];
    const int tid  = threadIdx.x;
    const int wid  = tid >> 5, lane = tid & 31;
    const int row0 = blockIdx.x * 128;
    const uint32_t smu = smem_u32(sm);

    // loader mapping: A row = tid&127, k-half (16 floats) = tid>>7
    const int lr = tid & 127;
    const int lh = tid >> 7;
    const float* aPtr = A + (size_t)(row0 + lr) * D_K + lh * 16;

    // warp tile: 4 M-warps x 2 N-warps; warp computes 32 x 80
    const int m0 = (wid & 3) * 32;
    const int n0 = (wid >> 2) * 80;

    // ldmatrix per-lane constants: row-in-tile, k sub-offset
    const int frow = lane & 15;
    const int fk   = (lane >> 4) * 8;

    float acc[2][10][4];
    #pragma unroll
    for (int mt = 0; mt < 2; mt++)
        #pragma unroll
        for (int j = 0; j < 10; j++)
            #pragma unroll
            for (int e = 0; e < 4; e++) acc[mt][j][e] = 0.0f;

    float4 av[4];

    // ---- helpers as lambdas ----
    auto loadA = [&](int kt) {
        #pragma unroll
        for (int q = 0; q < 4; q++) av[q] = *(const float4*)(aPtr + kt + q * 4);
    };
    auto cpB = [&](int kt, int s) {
        uint32_t bBase = smu + s * STAGE + 20480;
        #pragma unroll
        for (int p = 0; p < 5; p++) {
            int i = tid + p * 256;              // 0..1279
            int half = (i >= 640) ? 1 : 0;
            int j = i - half * 640;
            int n = j >> 2, seg = j & 3;
            const __nv_bfloat16* src =
                (half ? g_Bl : g_Bh) + (size_t)n * D_K + kt + seg * 8;
            uint32_t dst = bBase + half * 12800 + n * 80 + seg * 16;
            CP16(dst, src);
        }
    };
    auto stsA = [&](int s) {
        uint32_t hi[8], lo[8];
        #pragma unroll
        for (int q = 0; q < 4; q++) {
            split2(av[q].x, av[q].y, hi[2 * q], lo[2 * q]);
            split2(av[q].z, av[q].w, hi[2 * q + 1], lo[2 * q + 1]);
        }
        uint32_t aB = smu + s * STAGE + lr * 80 + lh * 32;
        *(uint4*)(sm + (aB - smu))           = make_uint4(hi[0], hi[1], hi[2], hi[3]);
        *(uint4*)(sm + (aB - smu) + 16)      = make_uint4(hi[4], hi[5], hi[6], hi[7]);
        *(uint4*)(sm + (aB - smu) + 10240)   = make_uint4(lo[0], lo[1], lo[2], lo[3]);
        *(uint4*)(sm + (aB - smu) + 10256)   = make_uint4(lo[4], lo[5], lo[6], lo[7]);
    };
    auto compute = [&](int s) {
        uint32_t ahiB = smu + s * STAGE;
        uint32_t aloB = ahiB + 10240;
        uint32_t bhiB = ahiB + 20480;
        uint32_t bloB = ahiB + 33280;
        #pragma unroll
        for (int ks = 0; ks < 2; ks++) {
            int kk = ks * 16 + fk;                      // element offset in k
            uint32_t af[2][2][4];
            #pragma unroll
            for (int mt = 0; mt < 2; mt++) {
                uint32_t ra = (uint32_t)((m0 + mt * 16 + frow) * 80 + kk * 2);
                LDSM_X4(af[mt][0][0], af[mt][0][1], af[mt][0][2], af[mt][0][3], ahiB + ra);
                LDSM_X4(af[mt][1][0], af[mt][1][1], af[mt][1][2], af[mt][1][3], aloB + ra);
            }
            uint32_t bfr[2][10][2];
            #pragma unroll
            for (int g = 0; g < 5; g++) {
                uint32_t rb = (uint32_t)((n0 + g * 16 + frow) * 80 + kk * 2);
                uint32_t r0, r1, r2, r3;
                LDSM_X4(r0, r1, r2, r3, bhiB + rb);
                bfr[0][2 * g][0] = r0; bfr[0][2 * g][1] = r2;
                bfr[0][2 * g + 1][0] = r1; bfr[0][2 * g + 1][1] = r3;
                LDSM_X4(r0, r1, r2, r3, bloB + rb);
                bfr[1][2 * g][0] = r0; bfr[1][2 * g][1] = r2;
                bfr[1][2 * g + 1][0] = r1; bfr[1][2 * g + 1][1] = r3;
            }
            #pragma unroll
            for (int mt = 0; mt < 2; mt++)
                #pragma unroll
                for (int j = 0; j < 10; j++) {
                    MMA_BF16(acc[mt][j], af[mt][0], bfr[0][j]);  // Ah*Bh
                    MMA_BF16(acc[mt][j], af[mt][0], bfr[1][j]);  // Ah*Bl
                    MMA_BF16(acc[mt][j], af[mt][1], bfr[0][j]);  // Al*Bh
                }
        }
    };

    // ---- pipeline: 64 chunks of BK=32 ----
    loadA(0);
    cpB(0, 0);
    CP_COMMIT();
    stsA(0);
    CP_WAIT0();
    __syncthreads();

    for (int ck = 0; ck < 64; ck++) {
        int s = ck & 1;
        if (ck < 63) {
            loadA((ck + 1) * 32);
            cpB((ck + 1) * 32, s ^ 1);
            CP_COMMIT();
        }
        compute(s);
        if (ck < 63) {
            stsA(s ^ 1);
            CP_WAIT0();
            __syncthreads();
        }
    }
    __syncthreads();

    // ---- stage logits (+bias) into SMEM, [128][160] f32 (reuses buffers) ----
    float* Ls = (float*)sm;
    {
        const int rr = lane >> 2;
        const int cc = (lane & 3) * 2;
        #pragma unroll
        for (int mt = 0; mt < 2; mt++)
            #pragma unroll
            for (int j = 0; j < 10; j++) {
                int r = m0 + mt * 16 + rr;
                int c = n0 + j * 8 + cc;
                float b0 = g_bias[c], b1 = g_bias[c + 1];
                Ls[r * 160 + c]           = acc[mt][j][0] + b0;
                Ls[r * 160 + c + 1]       = acc[mt][j][1] + b1;
                Ls[(r + 8) * 160 + c]     = acc[mt][j][2] + b0;
                Ls[(r + 8) * 160 + c + 1] = acc[mt][j][3] + b1;
            }
    }
    __syncthreads();

    // ---- epilogue: 128 rows x 8 top-labels = 1024 tasks, 4/thread ----
    #pragma unroll
    for (int p = 0; p < 4; p++) {
        int task = tid + p * 256;
        int r = task >> 3, t = task & 7;
        const float* Lr = Ls + r * 160;

        float gate = 1.0f / (1.0f + __expf(-Lr[128 + t]));

        float l[16], mx = -1e30f;
        #pragma unroll
        for (int c = 0; c < 16; c++) {
            l[c] = Lr[t * 16 + c];
            mx = fmaxf(mx, l[c]);
        }
        float ssum = 0.0f;
        #pragma unroll
        for (int c = 0; c < 16; c++) { l[c] = __expf(l[c] - mx); ssum += l[c]; }
        float sc = gate / ssum;

        float* op = out + (size_t)(row0 + r) * 128 + t * 16;
        #pragma unroll
        for (int q = 0; q < 4; q++) {
            float4 v;
            v.x = l[q * 4 + 0] * sc;
            v.y = l[q * 4 + 1] * sc;
            v.z = l[q * 4 + 2] * sc;
            v.w = l[q * 4 + 3] * sc;
            ((float4*)op)[q] = v;
        }
    }
}

// ---------------------------------------------------------------------------
extern "C" void kernel_launch(void* const* d_in, const int* in_sizes, int n_in,
                              void* d_out, int out_size) {
    const float* features = (const float*)d_in[0];
    const float* topW     = (const float*)d_in[1];
    const float* topb     = (const float*)d_in[2];
    const float* botW     = (const float*)d_in[3];
    const float* botb     = (const float*)d_in[4];
    float* out = (float*)d_out;

    cudaFuncSetAttribute(hc_mma_kernel,
                         cudaFuncAttributeMaxDynamicSharedMemorySize, SMEM_DYN);

    pack_kernel<<<(N_PAD * D_K + 255) / 256, 256>>>(topW, topb, botW, botb);
    hc_mma_kernel<<<16384 / 128, 256, SMEM_DYN>>>(features, out);
}

// round 5
// speedup vs baseline: 3.1296x; 1.1940x over previous
#include <cuda_runtime.h>
#include <cuda_bf16.h>
#include <stdint.h>
#include <math.h>

// ---------------------------------------------------------------------------
// HierarchicalClassifier via warp-level bf16 mma.sync (HMMA) on sm_103a.
//   logits[16384,136] = features[16384,2048] @ Wpacked[2048,136] + bias
//   fp32 emulated: Ah*Bh + Ah*Bl + Al*Bh (bf16 hi/lo split, 3 MMAs).
//   Packed cols: [0,128) bottom (t=n>>4, c=n&15), [128,136) top gate, pad->144.
// R4: BN=144 (was 160), BK=64 (was 32), restructured B-frag live ranges.
// ---------------------------------------------------------------------------

#define D_K   2048
#define N_PAD 144
#define N_REAL 136

__device__ __nv_bfloat16 g_Bh[N_PAD * D_K];   // [n][k] K-major
__device__ __nv_bfloat16 g_Bl[N_PAD * D_K];
__device__ float         g_bias[N_PAD];

// ---------------------------------------------------------------------------
__global__ void pack_kernel(const float* __restrict__ topW,
                            const float* __restrict__ topb,
                            const float* __restrict__ botW,
                            const float* __restrict__ botb) {
    int idx = blockIdx.x * blockDim.x + threadIdx.x;
    if (idx < N_PAD * D_K) {
        int n = idx / D_K, k = idx - n * D_K;
        float v = 0.0f;
        if (n < 128) {
            int t = n >> 4, c = n & 15;
            v = botW[((size_t)t * D_K + k) * 16 + c];
        } else if (n < N_REAL) {
            v = topW[(n - 128) * D_K + k];
        }
        __nv_bfloat16 hi = __float2bfloat16(v);
        g_Bh[idx] = hi;
        g_Bl[idx] = __float2bfloat16(v - __bfloat162float(hi));
    }
    if (idx < N_PAD) {
        float b = 0.0f;
        if (idx < 128)         b = botb[idx];
        else if (idx < N_REAL) b = topb[idx - 128];
        g_bias[idx] = b;
    }
}

// ---------------------------------------------------------------------------
__device__ __forceinline__ uint32_t smem_u32(const void* p) {
    uint32_t a;
    asm("{ .reg .u64 t; cvta.to.shared.u64 t, %1; cvt.u32.u64 %0, t; }"
        : "=r"(a) : "l"(p));
    return a;
}

#define LDSM_X4(r0, r1, r2, r3, addr) \
    asm volatile("ldmatrix.sync.aligned.m8n8.x4.shared.b16 {%0,%1,%2,%3}, [%4];" \
        : "=r"(r0), "=r"(r1), "=r"(r2), "=r"(r3) : "r"(addr))

#define LDSM_X2(r0, r1, addr) \
    asm volatile("ldmatrix.sync.aligned.m8n8.x2.shared.b16 {%0,%1}, [%2];" \
        : "=r"(r0), "=r"(r1) : "r"(addr))

#define MMA_BF16(d, a, b0, b1) \
    asm volatile("mma.sync.aligned.m16n8k16.row.col.f32.bf16.bf16.f32 " \
        "{%0,%1,%2,%3}, {%4,%5,%6,%7}, {%8,%9}, {%0,%1,%2,%3};" \
        : "+f"((d)[0]), "+f"((d)[1]), "+f"((d)[2]), "+f"((d)[3]) \
        : "r"((a)[0]), "r"((a)[1]), "r"((a)[2]), "r"((a)[3]), \
          "r"(b0), "r"(b1))

#define CP16(dst, src) \
    asm volatile("cp.async.cg.shared.global [%0], [%1], 16;" \
        :: "r"(dst), "l"(src) : "memory")
#define CP_COMMIT() asm volatile("cp.async.commit_group;" ::: "memory")
#define CP_WAIT0()  asm volatile("cp.async.wait_group 0;" ::: "memory")

__device__ __forceinline__ void split2(float v0, float v1, uint32_t& h, uint32_t& l) {
    uint32_t hp;
    asm("cvt.rn.bf16x2.f32 %0, %1, %2;" : "=r"(hp) : "f"(v1), "f"(v0));
    float h0 = __uint_as_float(hp << 16);
    float h1 = __uint_as_float(hp & 0xffff0000u);
    uint32_t lp;
    asm("cvt.rn.bf16x2.f32 %0, %1, %2;" : "=r"(lp) : "f"(v1 - h1), "f"(v0 - h0));
    h = hp; l = lp;
}

// ---------------------------------------------------------------------------
// Stage layout (row pitch 144B: 64 k-elems * 2B = 128B data + 16B pad ->
// conflict-free LDSM phases, 16B-aligned STS):
//   Ahi @0      (128*144 = 18432)
//   Alo @18432
//   Bhi @36864  (144*144 = 20736)
//   Blo @57600            STAGE = 78336, double buffered.
// ---------------------------------------------------------------------------
constexpr int PITCH    = 144;
constexpr int AHI_OFF  = 0;
constexpr int ALO_OFF  = 18432;
constexpr int BHI_OFF  = 36864;
constexpr int BLO_OFF  = 57600;
constexpr int STAGE    = 78336;
constexpr int SMEM_DYN = 2 * STAGE;   // 156672

__global__ __launch_bounds__(256, 1)
void hc_mma_kernel(const float* __restrict__ A, float* __restrict__ out) {
    extern __shared__ char sm[];
    const int tid  = threadIdx.x;
    const int wid  = tid >> 5, lane = tid & 31;
    const int row0 = blockIdx.x * 128;
    const uint32_t smu = smem_u32(sm);

    // A loader: row = tid>>1, k-half (32 floats) = tid&1
    const int lr = tid >> 1;
    const int lh = tid & 1;
    const float* aPtr = A + (size_t)(row0 + lr) * D_K + lh * 32;

    // warp tile: 4 M-warps x 2 N-warps; warp computes 32 x 72
    const int m0 = (wid & 3) * 32;
    const int n0 = (wid >> 2) * 72;

    const int frow = lane & 15;
    const int fk   = (lane >> 4) * 8;        // 0 or 8 (elements)
    // x2 lane mapping: rows n..n+7, k-low (lanes 0-7) / k-high (lanes 8-15)
    const int x2row = lane & 7;
    const int x2k   = ((lane >> 3) & 1) * 8;

    float acc[2][9][4];
    #pragma unroll
    for (int mt = 0; mt < 2; mt++)
        #pragma unroll
        for (int j = 0; j < 9; j++)
            #pragma unroll
            for (int e = 0; e < 4; e++) acc[mt][j][e] = 0.0f;

    float4 av[8];

    auto loadA = [&](int kt) {
        #pragma unroll
        for (int q = 0; q < 8; q++) av[q] = *(const float4*)(aPtr + kt + q * 4);
    };
    auto cpB = [&](int kt, int s) {
        uint32_t bBase = smu + s * STAGE + BHI_OFF;
        #pragma unroll
        for (int p = 0; p < 9; p++) {
            int i = tid + p * 256;                 // 0..2303
            int half = (i >= 1152) ? 1 : 0;
            int j = i - half * 1152;
            int n = j >> 3, seg = j & 7;           // n 0..143, seg 0..7 (16B units)
            const __nv_bfloat16* src =
                (half ? g_Bl : g_Bh) + (size_t)n * D_K + kt + seg * 8;
            uint32_t dst = bBase + half * 20736 + n * PITCH + seg * 16;
            CP16(dst, src);
        }
    };
    auto stsA = [&](int s) {
        uint32_t hi[16], lo[16];
        #pragma unroll
        for (int q = 0; q < 8; q++) {
            split2(av[q].x, av[q].y, hi[2 * q], lo[2 * q]);
            split2(av[q].z, av[q].w, hi[2 * q + 1], lo[2 * q + 1]);
        }
        char* aB = sm + s * STAGE + lr * PITCH + lh * 64;
        #pragma unroll
        for (int q = 0; q < 4; q++) {
            *(uint4*)(aB + AHI_OFF + q * 16) =
                make_uint4(hi[4 * q], hi[4 * q + 1], hi[4 * q + 2], hi[4 * q + 3]);
            *(uint4*)(aB + ALO_OFF + q * 16) =
                make_uint4(lo[4 * q], lo[4 * q + 1], lo[4 * q + 2], lo[4 * q + 3]);
        }
    };
    auto compute = [&](int s) {
        uint32_t stg = smu + s * STAGE;
        #pragma unroll
        for (int ks = 0; ks < 4; ks++) {
            int kk = ks * 16;
            // A frags: hi + lo, 2 m-tiles
            uint32_t ah[2][4], al[2][4];
            #pragma unroll
            for (int mt = 0; mt < 2; mt++) {
                uint32_t ra = (uint32_t)((m0 + mt * 16 + frow) * PITCH + (kk + fk) * 2);
                LDSM_X4(ah[mt][0], ah[mt][1], ah[mt][2], ah[mt][3], stg + AHI_OFF + ra);
                LDSM_X4(al[mt][0], al[mt][1], al[mt][2], al[mt][3], stg + ALO_OFF + ra);
            }
            // B: 4 full 16-col groups, frags consumed immediately
            #pragma unroll
            for (int g = 0; g < 4; g++) {
                uint32_t rb = (uint32_t)((n0 + g * 16 + frow) * PITCH + (kk + fk) * 2);
                uint32_t h0, h1, h2, h3, l0, l1, l2, l3;
                LDSM_X4(h0, h1, h2, h3, stg + BHI_OFF + rb);
                LDSM_X4(l0, l1, l2, l3, stg + BLO_OFF + rb);
                #pragma unroll
                for (int mt = 0; mt < 2; mt++) {
                    MMA_BF16(acc[mt][2 * g],     ah[mt], h0, h2);
                    MMA_BF16(acc[mt][2 * g],     ah[mt], l0, l2);
                    MMA_BF16(acc[mt][2 * g],     al[mt], h0, h2);
                    MMA_BF16(acc[mt][2 * g + 1], ah[mt], h1, h3);
                    MMA_BF16(acc[mt][2 * g + 1], ah[mt], l1, l3);
                    MMA_BF16(acc[mt][2 * g + 1], al[mt], h1, h3);
                }
            }
            // trailing 8-col group (j=8) via ldmatrix.x2
            {
                uint32_t rb = (uint32_t)((n0 + 64 + x2row) * PITCH + (kk + x2k) * 2);
                uint32_t h0, h1, l0, l1;
                LDSM_X2(h0, h1, stg + BHI_OFF + rb);
                LDSM_X2(l0, l1, stg + BLO_OFF + rb);
                #pragma unroll
                for (int mt = 0; mt < 2; mt++) {
                    MMA_BF16(acc[mt][8], ah[mt], h0, h1);
                    MMA_BF16(acc[mt][8], ah[mt], l0, l1);
                    MMA_BF16(acc[mt][8], al[mt], h0, h1);
                }
            }
        }
    };

    // ---- pipeline: 32 chunks of BK=64 ----
    loadA(0);
    cpB(0, 0);
    CP_COMMIT();
    stsA(0);
    CP_WAIT0();
    __syncthreads();

    for (int ck = 0; ck < 32; ck++) {
        int s = ck & 1;
        if (ck < 31) {
            loadA((ck + 1) * 64);
            cpB((ck + 1) * 64, s ^ 1);
            CP_COMMIT();
        }
        compute(s);
        if (ck < 31) {
            stsA(s ^ 1);
            CP_WAIT0();
            __syncthreads();
        }
    }
    __syncthreads();

    // ---- stage logits (+bias) into SMEM, [128][144] f32 (56.6KB + pad) ----
    float* Ls = (float*)sm;
    {
        const int rr = lane >> 2;
        const int cc = (lane & 3) * 2;
        #pragma unroll
        for (int mt = 0; mt < 2; mt++)
            #pragma unroll
            for (int j = 0; j < 9; j++) {
                int r = m0 + mt * 16 + rr;
                int c = n0 + j * 8 + cc;
                float b0 = g_bias[c], b1 = g_bias[c + 1];
                Ls[r * N_PAD + c]           = acc[mt][j][0] + b0;
                Ls[r * N_PAD + c + 1]       = acc[mt][j][1] + b1;
                Ls[(r + 8) * N_PAD + c]     = acc[mt][j][2] + b0;
                Ls[(r + 8) * N_PAD + c + 1] = acc[mt][j][3] + b1;
            }
    }
    __syncthreads();

    // ---- epilogue: 128 rows x 8 top-labels = 1024 tasks, 4/thread ----
    #pragma unroll
    for (int p = 0; p < 4; p++) {
        int task = tid + p * 256;
        int r = task >> 3, t = task & 7;
        const float* Lr = Ls + r * N_PAD;

        float gate = 1.0f / (1.0f + __expf(-Lr[128 + t]));

        float l[16], mx = -1e30f;
        #pragma unroll
        for (int c = 0; c < 16; c++) {
            l[c] = Lr[t * 16 + c];
            mx = fmaxf(mx, l[c]);
        }
        float ssum = 0.0f;
        #pragma unroll
        for (int c = 0; c < 16; c++) { l[c] = __expf(l[c] - mx); ssum += l[c]; }
        float sc = gate / ssum;

        float* op = out + (size_t)(row0 + r) * 128 + t * 16;
        #pragma unroll
        for (int q = 0; q < 4; q++) {
            float4 v;
            v.x = l[q * 4 + 0] * sc;
            v.y = l[q * 4 + 1] * sc;
            v.z = l[q * 4 + 2] * sc;
            v.w = l[q * 4 + 3] * sc;
            ((float4*)op)[q] = v;
        }
    }
}

// ---------------------------------------------------------------------------
extern "C" void kernel_launch(void* const* d_in, const int* in_sizes, int n_in,
                              void* d_out, int out_size) {
    const float* features = (const float*)d_in[0];
    const float* topW     = (const float*)d_in[1];
    const float* topb     = (const float*)d_in[2];
    const float* botW     = (const float*)d_in[3];
    const float* botb     = (const float*)d_in[4];
    float* out = (float*)d_out;

    cudaFuncSetAttribute(hc_mma_kernel,
                         cudaFuncAttributeMaxDynamicSharedMemorySize, SMEM_DYN);

    pack_kernel<<<(N_PAD * D_K + 255) / 256, 256>>>(topW, topb, botW, botb);
    hc_mma_kernel<<<16384 / 128, 256, SMEM_DYN>>>(features, out);
}